// round 8
// baseline (speedup 1.0000x reference)
#include <cuda_runtime.h>

// YOLO detection-head decode:
//   in : (64, 255, 52, 52) f32, channel-major, spatial contiguous
//   out: (64, 8112, 85)   f32, attr-last contiguous
//
// R8 (= R2..R7 resubmit; all prior attempts hit GPU-acquisition infra
// failures and never ran): smem holds the tile in OUTPUT layout [sl][85] so
// the store phase is a flat float4 copy (LDS.128 + STG.128, no index math).
// Load phase is scalar: block (104,4); tx = spatial-in-tile, c = ty + 4*i.
// STS lane stride = 85 floats -> bank stride 21 (gcd 21,32 = 1) ->
// conflict-free. No div/mod anywhere in the kernel.

#define GDIM     52
#define SPATIAL  2704          // 52*52
#define NATTR    85
#define S_TILE   104           // 2 grid rows; 2704/104 = 26 exact
#define TILES    26
#define NTHREADS 416           // 104 x 4

__global__ __launch_bounds__(NTHREADS)
void yolo_decode_kernel(const float* __restrict__ in, float* __restrict__ out) {
    // Tile in output layout: [sl][c], leading dim exactly NATTR.
    __shared__ __align__(16) float sm[S_TILE * NATTR];   // 35,360 B

    const int tile  = blockIdx.x % TILES;
    const int plane = blockIdx.x / TILES;    // b*3 + a
    const int a     = plane % 3;

    // output = exp(tw) * (anchor/stride) * stride = exp(tw) * anchor_px
    const float aw = (a == 0) ? 10.0f : (a == 1) ? 16.0f : 33.0f;
    const float ah = (a == 0) ? 13.0f : (a == 1) ? 30.0f : 23.0f;

    const int tx = threadIdx.x;              // 0..103 : spatial within tile
    const int ty = threadIdx.y;              // 0..3   : attr phase

    const int s0 = tile * S_TILE;
    const float gx = (float)((tx < GDIM) ? tx : tx - GDIM);
    const float gy = (float)(tile * 2 + ((tx >= GDIM) ? 1 : 0));

    const float* inp = in + (size_t)plane * NATTR * SPATIAL + s0 + tx;
    float* smrow = sm + tx * NATTR;

    // ---- Load + transform: one scalar element per thread per iteration ----
    #pragma unroll 4
    for (int c = ty; c < NATTR; c += 4) {
        const float x = __ldg(inp + (size_t)c * SPATIAL);
        float o;
        if (c >= 4) {
            o = __frcp_rn(1.0f + __expf(-x));           // conf + classes
        } else if (c == 0) {
            o = (__frcp_rn(1.0f + __expf(-x)) + gx) * 8.0f;
        } else if (c == 1) {
            o = (__frcp_rn(1.0f + __expf(-x)) + gy) * 8.0f;
        } else if (c == 2) {
            o = __expf(x) * aw;
        } else {                                        // c == 3
            o = __expf(x) * ah;
        }
        smrow[c] = o;
    }
    __syncthreads();

    // ---- Store: tile is bit-identical to the output image -> flat copy ----
    const float4* sm4 = reinterpret_cast<const float4*>(sm);
    float4* outp = reinterpret_cast<float4*>(out + ((size_t)plane * SPATIAL + s0) * NATTR);
    const int tid = ty * S_TILE + tx;
    #pragma unroll 6
    for (int f = tid; f < (S_TILE * NATTR) / 4; f += NTHREADS) {
        outp[f] = sm4[f];
    }
}

extern "C" void kernel_launch(void* const* d_in, const int* in_sizes, int n_in,
                              void* d_out, int out_size) {
    const float* x = (const float*)d_in[0];
    float* out = (float*)d_out;
    dim3 block(S_TILE, 4);
    const int nblocks = 64 * 3 * TILES;      // 4992
    yolo_decode_kernel<<<nblocks, block>>>(x, out);
}